// round 8
// baseline (speedup 1.0000x reference)
#include <cuda_runtime.h>

#define NQ    12
#define DEPTH 6
#define TPB   32

typedef unsigned int u32;

// ---------------------------------------------------------------------------
// Wire q <-> flat-index bit (11-q). CNOT ring tracked as GF(2)-linear storage
// permutation; Q_d = F^d columns precomputed (with smem swizzle composed in).
// ---------------------------------------------------------------------------
__host__ __device__ constexpr u32 Fmap(u32 b) {
    for (int g = 11; g >= 0; --g) {
        int c = 11 - g, t = (c + 11) % NQ;
        b ^= ((b >> c) & 1u) << t;
    }
    return b;
}
__host__ __device__ constexpr u32 Finvmap(u32 b) {
    for (int g = 0; g < NQ; ++g) {
        int c = 11 - g, t = (c + 11) % NQ;
        b ^= ((b >> c) & 1u) << t;
    }
    return b;
}
__host__ __device__ constexpr u32 swz(u32 x) { return x ^ ((x >> 5) & 31u); }

struct Tabs {
    u32 q[DEPTH][NQ];  // swizzled columns of Q_d = F^d
    u32 finv[NQ];      // columns of F^{-1} (logical space, for final weights)
};
__host__ __device__ constexpr Tabs mk_tabs() {
    Tabs t{};
    u32 raw[NQ] = {};
    for (int j = 0; j < NQ; ++j) { raw[j] = 1u << j; t.q[0][j] = swz(raw[j]); }
    for (int d = 1; d < DEPTH; ++d)
        for (int j = 0; j < NQ; ++j) { raw[j] = Fmap(raw[j]); t.q[d][j] = swz(raw[j]); }
    for (int j = 0; j < NQ; ++j) t.finv[j] = Finvmap(1u << j);
    return t;
}
__constant__ Tabs TAB = mk_tabs();

// Pass p: 5 register bit-directions DIRS[p] (gates on first 4);
// FILL[p][0..4] -> lane bits (tid), FILL[p][5..6] -> serial chunk bits.
__constant__ int DIRS[3][5] = {{0,1,2,3,4},{4,5,6,7,8},{8,9,10,11,0}};
__constant__ int FILL[3][7] = {{5,6,7,8,9,10,11},{0,1,2,3,9,10,11},{1,2,3,4,5,6,7}};

__device__ __forceinline__ float2 cmul(float2 a, float2 b) {
    return make_float2(fmaf(a.x, b.x, -a.y * b.y), fmaf(a.x, b.y, a.y * b.x));
}

__global__ void __launch_bounds__(TPB)
qsim_kernel(const float* __restrict__ inp, const float* __restrict__ wp,
            float* __restrict__ out)
{
    __shared__ float2 sv[1 << NQ];               // 32 KB state, warp-private
    __shared__ float2 gms[DEPTH * NQ * 2];       // m00,m01 per gate (SU(2))
    __shared__ float2 vtab[NQ][2];               // per-qubit prep 2-vectors

    const int t   = threadIdx.x;                 // 0..31
    const int bid = blockIdx.x;

    // ---- tables ------------------------------------------------------------
    if (t < NQ) {
        // fold encode RY(x) with layer-1 Rot into one complex 2-vector/qubit
        float x = inp[bid * NQ + (11 - t)];      // bit t <- wire 11-t
        float sx, cx; sincosf(0.5f * x, &sx, &cx);
        int wo = (11 - t) * 3;                   // w[0][wire]
        float phi = wp[wo + 0], th = wp[wo + 1], om = wp[wo + 2];
        float st, ct; sincosf(0.5f * th, &st, &ct);
        float sa, ca; sincosf(0.5f * (phi + om), &sa, &ca);
        float sb, cb; sincosf(0.5f * (phi - om), &sb, &cb);
        float2 m00 = make_float2( ct * ca, -ct * sa);
        float2 m01 = make_float2(-st * cb, -st * sb);
        float2 m10 = make_float2( st * cb, -st * sb);   // = -conj(m01)
        float2 m11 = make_float2( ct * ca,  ct * sa);   // =  conj(m00)
        vtab[t][0] = make_float2(fmaf(m00.x, cx, m01.x * sx), fmaf(m00.y, cx, m01.y * sx));
        vtab[t][1] = make_float2(fmaf(m10.x, cx, m11.x * sx), fmaf(m10.y, cx, m11.y * sx));
    }
    for (int i = NQ + t; i < DEPTH * NQ; i += TPB) {   // layers 2..6 gates
        int d = i / NQ, m = i % NQ;              // m = bit index, wire = 11-m
        int wo = (d * NQ + (11 - m)) * 3;
        float phi = wp[wo + 0], th = wp[wo + 1], om = wp[wo + 2];
        float st, ct; sincosf(0.5f * th, &st, &ct);
        float sa, ca; sincosf(0.5f * (phi + om), &sa, &ca);
        float sb, cb; sincosf(0.5f * (phi - om), &sb, &cb);
        gms[i * 2 + 0] = make_float2( ct * ca, -ct * sa);   // m00
        gms[i * 2 + 1] = make_float2(-st * cb, -st * sb);   // m01
    }
    __syncwarp();

    // ---- prep: psi_1 = encode + layer-1 Rot (product state), 4 chunks ------
    {
        const u32* qc = TAB.q[0];
        u32 qd[5];
        #pragma unroll
        for (int k = 0; k < 5; ++k) qd[k] = qc[DIRS[0][k]];
        u32 pbl = 0;
        #pragma unroll
        for (int j = 0; j < 5; ++j)
            if ((t >> j) & 1) pbl ^= qc[FILL[0][j]];
        const u32 cm0 = qc[FILL[0][5]], cm1 = qc[FILL[0][6]];

        float2 fl = vtab[FILL[0][0]][t & 1];
        #pragma unroll
        for (int j = 1; j < 5; ++j) fl = cmul(fl, vtab[FILL[0][j]][(t >> j) & 1]);

        #pragma unroll
        for (int k = 0; k < 4; ++k) {
            u32 pb = pbl ^ ((k & 1) ? cm0 : 0u) ^ ((k & 2) ? cm1 : 0u);
            float2 f = cmul(cmul(fl, vtab[FILL[0][5]][k & 1]),
                            vtab[FILL[0][6]][(k >> 1) & 1]);
            float2 v[32]; v[0] = f;
            #pragma unroll
            for (int j = 0; j < 5; ++j) {
                #pragma unroll
                for (int c = 0; c < (1 << j); ++c) {
                    float2 lo = v[c];
                    v[c]            = cmul(lo, vtab[DIRS[0][j]][0]);
                    v[c + (1 << j)] = cmul(lo, vtab[DIRS[0][j]][1]);
                }
            }
            #pragma unroll
            for (int c = 0; c < 32; ++c) {
                u32 a = pb;
                if (c & 1)  a ^= qd[0];
                if (c & 2)  a ^= qd[1];
                if (c & 4)  a ^= qd[2];
                if (c & 8)  a ^= qd[3];
                if (c & 16) a ^= qd[4];
                sv[a] = v[c];
            }
        }
    }
    __syncwarp();

    float acc = 0.f;

    // ---- variational layers 2..6 -------------------------------------------
    for (int d = 1; d < DEPTH; ++d) {
        const u32* qc = TAB.q[d];
        for (int p = 0; p < 3; ++p) {
            u32 qd[5];
            #pragma unroll
            for (int k = 0; k < 5; ++k) qd[k] = qc[DIRS[p][k]];
            u32 pbl = 0;
            #pragma unroll
            for (int j = 0; j < 5; ++j)
                if ((t >> j) & 1) pbl ^= qc[FILL[p][j]];
            const u32 cm0 = qc[FILL[p][5]], cm1 = qc[FILL[p][6]];

            const float2* g2 = &gms[(d * NQ + p * 4) * 2];
            float2 gu[4], gv[4];
            #pragma unroll
            for (int g = 0; g < 4; ++g) { gu[g] = g2[2*g]; gv[g] = g2[2*g+1]; }

            const bool last = (d == DEPTH - 1 && p == 2);
            u32 fbl = 0, fd[5], fc0 = 0, fc1 = 0;
            if (last) {
                #pragma unroll
                for (int j = 0; j < 5; ++j)
                    if ((t >> j) & 1) fbl ^= TAB.finv[FILL[2][j]];
                fc0 = TAB.finv[FILL[2][5]]; fc1 = TAB.finv[FILL[2][6]];
                #pragma unroll
                for (int k = 0; k < 5; ++k) fd[k] = TAB.finv[DIRS[2][k]];
            }

            #pragma unroll
            for (int k = 0; k < 4; ++k) {
                u32 pb = pbl ^ ((k & 1) ? cm0 : 0u) ^ ((k & 2) ? cm1 : 0u);
                float2 s[32];
                #pragma unroll
                for (int c = 0; c < 32; ++c) {
                    u32 a = pb;
                    if (c & 1)  a ^= qd[0];
                    if (c & 2)  a ^= qd[1];
                    if (c & 4)  a ^= qd[2];
                    if (c & 8)  a ^= qd[3];
                    if (c & 16) a ^= qd[4];
                    s[c] = sv[a];
                }
                #pragma unroll
                for (int g = 0; g < 4; ++g) {
                    float2 u = gu[g], v = gv[g];
                    #pragma unroll
                    for (int c = 0; c < 32; ++c) {
                        if (!((c >> g) & 1)) {
                            float2 a0 = s[c], a1 = s[c | (1 << g)];
                            float2 n0, n1;
                            n0.x = fmaf(u.x, a0.x, fmaf(-u.y, a0.y, fmaf(v.x, a1.x, -v.y * a1.y)));
                            n0.y = fmaf(u.x, a0.y, fmaf( u.y, a0.x, fmaf(v.x, a1.y,  v.y * a1.x)));
                            n1.x = fmaf(u.x, a1.x, fmaf( u.y, a1.y, fmaf(-v.x, a0.x, -v.y * a0.y)));
                            n1.y = fmaf(u.x, a1.y, fmaf(-u.y, a1.x, fmaf( v.y, a0.x, -v.x * a0.y)));
                            s[c] = n0; s[c | (1 << g)] = n1;
                        }
                    }
                }
                if (last) {
                    u32 fb = fbl ^ ((k & 1) ? fc0 : 0u) ^ ((k & 2) ? fc1 : 0u);
                    #pragma unroll
                    for (int c = 0; c < 32; ++c) {
                        u32 fv = fb;
                        if (c & 1)  fv ^= fd[0];
                        if (c & 2)  fv ^= fd[1];
                        if (c & 4)  fv ^= fd[2];
                        if (c & 8)  fv ^= fd[3];
                        if (c & 16) fv ^= fd[4];
                        float wgt = (float)(NQ - 2 * __popc(fv));
                        acc = fmaf(fmaf(s[c].x, s[c].x, s[c].y * s[c].y), wgt, acc);
                    }
                } else {
                    #pragma unroll
                    for (int c = 0; c < 32; ++c) {
                        u32 a = pb;
                        if (c & 1)  a ^= qd[0];
                        if (c & 2)  a ^= qd[1];
                        if (c & 4)  a ^= qd[2];
                        if (c & 8)  a ^= qd[3];
                        if (c & 16) a ^= qd[4];
                        sv[a] = s[c];
                    }
                }
            }
            if (!last) __syncwarp();
        }
    }

    // ---- warp reduction -> out[bid] ----
    #pragma unroll
    for (int o = 16; o; o >>= 1) acc += __shfl_xor_sync(0xffffffffu, acc, o);
    if (t == 0) out[bid] = acc * (1.0f / NQ);
}

extern "C" void kernel_launch(void* const* d_in, const int* in_sizes, int n_in,
                              void* d_out, int out_size)
{
    const float *inp, *wp;
    if (in_sizes[0] == DEPTH * NQ * 3) {            // defensive input-order check
        wp  = (const float*)d_in[0];
        inp = (const float*)d_in[1];
    } else {
        inp = (const float*)d_in[0];
        wp  = (const float*)d_in[1];
    }
    cudaFuncSetAttribute(qsim_kernel,
                         cudaFuncAttributePreferredSharedMemoryCarveout, 100);
    int B = out_size;                                // [B,1] float output
    qsim_kernel<<<B, TPB>>>(inp, wp, (float*)d_out);
}

// round 9
// speedup vs baseline: 1.4613x; 1.4613x over previous
#include <cuda_runtime.h>

#define NQ    12
#define DEPTH 6
#define TPB   128

typedef unsigned int u32;

// ---------------------------------------------------------------------------
// Wire q <-> flat-index bit (11-q). CNOT ring tracked as GF(2)-linear storage
// permutation; Q_d = F^d columns precomputed (with smem swizzle composed in).
// ---------------------------------------------------------------------------
__host__ __device__ constexpr u32 Fmap(u32 b) {
    for (int g = 11; g >= 0; --g) {
        int c = 11 - g, t = (c + 11) % NQ;
        b ^= ((b >> c) & 1u) << t;
    }
    return b;
}
__host__ __device__ constexpr u32 Finvmap(u32 b) {
    for (int g = 0; g < NQ; ++g) {
        int c = 11 - g, t = (c + 11) % NQ;
        b ^= ((b >> c) & 1u) << t;
    }
    return b;
}
__host__ __device__ constexpr u32 swz(u32 x) { return x ^ ((x >> 5) & 31u); }

struct Tabs {
    u32 q[DEPTH][NQ];  // swizzled columns of Q_d = F^d
    u32 finv[NQ];      // columns of F^{-1} (logical space, for final weights)
};
__host__ __device__ constexpr Tabs mk_tabs() {
    Tabs t{};
    u32 raw[NQ] = {};
    for (int j = 0; j < NQ; ++j) { raw[j] = 1u << j; t.q[0][j] = swz(raw[j]); }
    for (int d = 1; d < DEPTH; ++d)
        for (int j = 0; j < NQ; ++j) { raw[j] = Fmap(raw[j]); t.q[d][j] = swz(raw[j]); }
    for (int j = 0; j < NQ; ++j) t.finv[j] = Finvmap(1u << j);
    return t;
}
__constant__ Tabs TAB = mk_tabs();

// 2 passes/layer. Pass p: register gate dirs DIRS2[p][0..4], shuffle-gate dir
// = FILL2[p][0] (lane bit 0). FILL2[p][j]: tid bit j -> logical dir.
__constant__ int DIRS2[2][5] = {{0,1,2,3,4},{6,7,8,9,10}};
__constant__ int FILL2[2][7] = {{5,6,7,8,9,10,11},{11,0,1,2,3,4,5}};

__device__ __forceinline__ float2 cmul(float2 a, float2 b) {
    return make_float2(fmaf(a.x, b.x, -a.y * b.y), fmaf(a.x, b.y, a.y * b.x));
}

__global__ void __launch_bounds__(TPB, 4)
qsim_kernel(const float* __restrict__ inp, const float* __restrict__ wp,
            float* __restrict__ out)
{
    __shared__ float2 sv[1 << NQ];               // 32 KB state (AoS re,im)
    __shared__ float2 gms[DEPTH * NQ * 2];       // m00,m01 per gate (SU(2))
    __shared__ float2 vtab[NQ][2];               // per-qubit prep 2-vectors
    __shared__ float  red[TPB / 32];

    const int t   = threadIdx.x;                 // 7 bits: 5 lane + 2 warp
    const int bid = blockIdx.x;

    // ---- per-block prep ----------------------------------------------------
    if (t < NQ) {
        // fold encode RY(x) with layer-1 Rot into one complex 2-vector/qubit
        float x = inp[bid * NQ + (11 - t)];      // bit t <- wire 11-t
        float sx, cx; sincosf(0.5f * x, &sx, &cx);
        int wo = (11 - t) * 3;                   // w[0][wire]
        float phi = wp[wo + 0], th = wp[wo + 1], om = wp[wo + 2];
        float st, ct; sincosf(0.5f * th, &st, &ct);
        float sa, ca; sincosf(0.5f * (phi + om), &sa, &ca);
        float sb, cb; sincosf(0.5f * (phi - om), &sb, &cb);
        float2 m00 = make_float2( ct * ca, -ct * sa);
        float2 m01 = make_float2(-st * cb, -st * sb);
        float2 m10 = make_float2( st * cb, -st * sb);   // = -conj(m01)
        float2 m11 = make_float2( ct * ca,  ct * sa);   // =  conj(m00)
        vtab[t][0] = make_float2(fmaf(m00.x, cx, m01.x * sx), fmaf(m00.y, cx, m01.y * sx));
        vtab[t][1] = make_float2(fmaf(m10.x, cx, m11.x * sx), fmaf(m10.y, cx, m11.y * sx));
    } else if (t < DEPTH * NQ) {
        // gate matrices for layers 2..6 (d = 1..5); SU(2): keep m00,m01 only
        int d = t / NQ, m = t % NQ;              // m = bit index, wire = 11-m
        int wo = (d * NQ + (11 - m)) * 3;
        float phi = wp[wo + 0], th = wp[wo + 1], om = wp[wo + 2];
        float st, ct; sincosf(0.5f * th, &st, &ct);
        float sa, ca; sincosf(0.5f * (phi + om), &sa, &ca);
        float sb, cb; sincosf(0.5f * (phi - om), &sb, &cb);
        gms[t * 2 + 0] = make_float2( ct * ca, -ct * sa);   // m00
        gms[t * 2 + 1] = make_float2(-st * cb, -st * sb);   // m01
    }
    __syncthreads();

    // ---- prep pass: build psi_1 (encode + layer-1 Rot) and store ----------
    {
        const u32* qc = TAB.q[0];
        u32 pb = 0;
        #pragma unroll
        for (int j = 0; j < 7; ++j)
            if ((t >> j) & 1) pb ^= qc[FILL2[0][j]];
        u32 qd[5];
        #pragma unroll
        for (int k = 0; k < 5; ++k) qd[k] = qc[DIRS2[0][k]];

        float2 f = vtab[FILL2[0][0]][t & 1];
        #pragma unroll
        for (int j = 1; j < 7; ++j) f = cmul(f, vtab[FILL2[0][j]][(t >> j) & 1]);
        float2 v[32]; v[0] = f;
        #pragma unroll
        for (int j = 0; j < 5; ++j) {
            #pragma unroll
            for (int k = 0; k < (1 << j); ++k) {
                float2 lo = v[k];
                v[k]            = cmul(lo, vtab[DIRS2[0][j]][0]);
                v[k + (1 << j)] = cmul(lo, vtab[DIRS2[0][j]][1]);
            }
        }
        #pragma unroll
        for (int c = 0; c < 32; ++c) {
            u32 a = pb;
            if (c & 1)  a ^= qd[0];
            if (c & 2)  a ^= qd[1];
            if (c & 4)  a ^= qd[2];
            if (c & 8)  a ^= qd[3];
            if (c & 16) a ^= qd[4];
            sv[a] = v[c];
        }
        __syncthreads();
    }

    float acc = 0.f;

    // ---- variational layers 2..6: 2 passes each ----------------------------
    for (int d = 1; d < DEPTH; ++d) {
        const u32* qc = TAB.q[d];
        for (int p = 0; p < 2; ++p) {
            u32 pb = 0;
            #pragma unroll
            for (int j = 0; j < 7; ++j)
                if ((t >> j) & 1) pb ^= qc[FILL2[p][j]];
            u32 qd[5];
            #pragma unroll
            for (int k = 0; k < 5; ++k) qd[k] = qc[DIRS2[p][k]];

            float2 s[32];
            #pragma unroll
            for (int c = 0; c < 32; ++c) {
                u32 a = pb;
                if (c & 1)  a ^= qd[0];
                if (c & 2)  a ^= qd[1];
                if (c & 4)  a ^= qd[2];
                if (c & 8)  a ^= qd[3];
                if (c & 16) a ^= qd[4];
                s[c] = sv[a];
            }

            // ---- 5 register-resident SU(2) gates on DIRS2[p] ---------------
            #pragma unroll
            for (int g = 0; g < 5; ++g) {
                const float2* g2 = &gms[(d * NQ + DIRS2[p][g]) * 2];
                float2 u = g2[0], v = g2[1];               // m00, m01
                #pragma unroll
                for (int c = 0; c < 32; ++c) {
                    if (!((c >> g) & 1)) {
                        float2 a0 = s[c], a1 = s[c | (1 << g)];
                        float2 n0, n1;
                        n0.x = fmaf(u.x, a0.x, fmaf(-u.y, a0.y, fmaf(v.x, a1.x, -v.y * a1.y)));
                        n0.y = fmaf(u.x, a0.y, fmaf( u.y, a0.x, fmaf(v.x, a1.y,  v.y * a1.x)));
                        n1.x = fmaf(u.x, a1.x, fmaf( u.y, a1.y, fmaf(-v.x, a0.x, -v.y * a0.y)));
                        n1.y = fmaf(u.x, a1.y, fmaf(-u.y, a1.x, fmaf( v.y, a0.x, -v.x * a0.y)));
                        s[c] = n0; s[c | (1 << g)] = n1;
                    }
                }
            }

            // ---- shuffle gate on dir FILL2[p][0] (lane bit 0) --------------
            {
                const float2* g2 = &gms[(d * NQ + FILL2[p][0]) * 2];
                float2 u = g2[0], v = g2[1];
                bool hi = (t & 1);
                float2 U = hi ? make_float2(u.x, -u.y) : u;        //  conj(m00)
                float2 V = hi ? make_float2(-v.x,  v.y) : v;       // -conj(m01)
                #pragma unroll
                for (int c = 0; c < 32; ++c) {
                    float2 a = s[c], b;
                    b.x = __shfl_xor_sync(0xffffffffu, a.x, 1);
                    b.y = __shfl_xor_sync(0xffffffffu, a.y, 1);
                    float2 n;
                    n.x = fmaf(U.x, a.x, fmaf(-U.y, a.y, fmaf(V.x, b.x, -V.y * b.y)));
                    n.y = fmaf(U.x, a.y, fmaf( U.y, a.x, fmaf(V.x, b.y,  V.y * b.x)));
                    s[c] = n;
                }
            }

            if (d == DEPTH - 1 && p == 1) {
                // ---- fold final ring + <Z> mean into the reduction ---------
                u32 fb = 0;
                #pragma unroll
                for (int j = 0; j < 7; ++j)
                    if ((t >> j) & 1) fb ^= TAB.finv[FILL2[1][j]];
                u32 fd[5];
                #pragma unroll
                for (int k = 0; k < 5; ++k) fd[k] = TAB.finv[DIRS2[1][k]];
                #pragma unroll
                for (int c = 0; c < 32; ++c) {
                    u32 fv = fb;
                    if (c & 1)  fv ^= fd[0];
                    if (c & 2)  fv ^= fd[1];
                    if (c & 4)  fv ^= fd[2];
                    if (c & 8)  fv ^= fd[3];
                    if (c & 16) fv ^= fd[4];
                    float wgt = (float)(NQ - 2 * __popc(fv));
                    acc = fmaf(fmaf(s[c].x, s[c].x, s[c].y * s[c].y), wgt, acc);
                }
            } else {
                #pragma unroll
                for (int c = 0; c < 32; ++c) {
                    u32 a = pb;
                    if (c & 1)  a ^= qd[0];
                    if (c & 2)  a ^= qd[1];
                    if (c & 4)  a ^= qd[2];
                    if (c & 8)  a ^= qd[3];
                    if (c & 16) a ^= qd[4];
                    sv[a] = s[c];
                }
                __syncthreads();
            }
        }
    }

    // ---- block reduction -> out[bid] ----
    #pragma unroll
    for (int o = 16; o; o >>= 1) acc += __shfl_xor_sync(0xffffffffu, acc, o);
    if ((t & 31) == 0) red[t >> 5] = acc;
    __syncthreads();
    if (t == 0)
        out[bid] = (red[0] + red[1] + red[2] + red[3]) * (1.0f / NQ);
}

extern "C" void kernel_launch(void* const* d_in, const int* in_sizes, int n_in,
                              void* d_out, int out_size)
{
    const float *inp, *wp;
    if (in_sizes[0] == DEPTH * NQ * 3) {            // defensive input-order check
        wp  = (const float*)d_in[0];
        inp = (const float*)d_in[1];
    } else {
        inp = (const float*)d_in[0];
        wp  = (const float*)d_in[1];
    }
    int B = out_size;                                // [B,1] float output
    qsim_kernel<<<B, TPB>>>(inp, wp, (float*)d_out);
}